// round 13
// baseline (speedup 1.0000x reference)
#include <cuda_runtime.h>
#include <cuda_bf16.h>
#include <math.h>
#include <stdint.h>

#define BB   32
#define SS   576
#define FFE  700
#define KP0  704
#define DD   16
#define KCB  1024
#define MM   (BB*SS)
#define E0   512
#define E1   256
#define E2   32
#define DEC0 1024
#define DEC1 512
#define NOUT (SS*FFE)
#define ZFD  (SS*DD)

#define REC_OFF  0
#define MEAN_OFF (BB*NOUT)
#define LV_OFF   (MEAN_OFF + MM*DD)
#define VQ_OFF   (LV_OFF + MM*DD)
#define NVQBLK   144

// ---------------- scratch (device globals) ----------------
__device__ uint16_t g_xh[MM*KP0],  g_xl[MM*KP0];
__device__ uint16_t g_w0h[E0*KP0], g_w0l[E0*KP0];
__device__ uint16_t g_w1h[E1*E0],  g_w1l[E1*E0];
__device__ uint16_t g_h0h[MM*E0],  g_h0l[MM*E0];
__device__ uint16_t g_a2h[BB*DEC1], g_a2l[BB*DEC1];
__device__ float g_h1[MM*E1];
__device__ float g_enc[MM*E2];
__device__ float g_ze[MM*DD];
__device__ float g_zq[MM*DD];
__device__ float g_hd0[BB*DEC0];
__device__ float g_hd1[BB*DEC1];
__device__ float g_vqpart[NVQBLK];

// ---------------- helpers ----------------
__device__ __forceinline__ uint32_t smem_u32(const void* p) {
    uint32_t a;
    asm("{ .reg .u64 t; cvta.to.shared.u64 t, %1; cvt.u32.u64 %0, t; }" : "=r"(a) : "l"(p));
    return a;
}
__device__ __forceinline__ void ldsm4(uint32_t& r0, uint32_t& r1, uint32_t& r2, uint32_t& r3, uint32_t addr) {
    asm volatile("ldmatrix.sync.aligned.m8n8.x4.shared.b16 {%0,%1,%2,%3}, [%4];"
        : "=r"(r0), "=r"(r1), "=r"(r2), "=r"(r3) : "r"(addr));
}
__device__ __forceinline__ void mma_bf16(float* d, const uint32_t* a, uint32_t b0, uint32_t b1) {
    asm volatile("mma.sync.aligned.m16n8k16.row.col.f32.bf16.bf16.f32 "
        "{%0,%1,%2,%3}, {%4,%5,%6,%7}, {%8,%9}, {%0,%1,%2,%3};"
        : "+f"(d[0]), "+f"(d[1]), "+f"(d[2]), "+f"(d[3])
        : "r"(a[0]), "r"(a[1]), "r"(a[2]), "r"(a[3]), "r"(b0), "r"(b1));
}
__device__ __forceinline__ uint32_t pack_bf2(float a, float b) {
    __nv_bfloat162 t = __floats2bfloat162_rn(a, b);
    return *(uint32_t*)&t;
}
__device__ __forceinline__ float bfr(float v) {
    return __bfloat162float(__float2bfloat16(v));
}
__device__ __forceinline__ uint32_t hi_pair(float a, float b) {
    uint32_t r;
    asm("prmt.b32 %0, %1, %2, 0x7632;" : "=r"(r) : "r"(__float_as_uint(a)), "r"(__float_as_uint(b)));
    return r;
}
__device__ __forceinline__ float hi_trunc(float v) {
    return __uint_as_float(__float_as_uint(v) & 0xFFFF0000u);
}

// ---------------- pre-split kernels ----------------
__global__ void split_rm(const float* __restrict__ src, uint16_t* __restrict__ hi,
                         uint16_t* __restrict__ lo, int K, int Kpad, int total)
{
    int i = blockIdx.x * 256 + threadIdx.x;
    if (i >= total) return;
    int r = i / Kpad, c = i % Kpad;
    float v = (c < K) ? src[(size_t)r * K + c] : 0.f;
    float h = bfr(v);
    __nv_bfloat16 hb = __float2bfloat16(h);
    __nv_bfloat16 lb = __float2bfloat16(v - h);
    hi[i] = *(uint16_t*)&hb;
    lo[i] = *(uint16_t*)&lb;
}
__global__ void split_tr(const float* __restrict__ src, uint16_t* __restrict__ hi,
                         uint16_t* __restrict__ lo, int K, int N, int Kpad, int total)
{
    int i = blockIdx.x * 256 + threadIdx.x;
    if (i >= total) return;
    int n = i / Kpad, k = i % Kpad;
    float v = (k < K) ? src[(size_t)k * N + n] : 0.f;
    float h = bfr(v);
    __nv_bfloat16 hb = __float2bfloat16(h);
    __nv_bfloat16 lb = __float2bfloat16(v - h);
    hi[i] = *(uint16_t*)&hb;
    lo[i] = *(uint16_t*)&lb;
}

// ======== MMA GEMM v3: BM=64 BN=128 BK=32; 4 warps 2(M)x2(N); occ 2; reg-prefetch ========
// Identical 32x64 warp tile / LDK=40 layout as the measured-good R8 config —
// only block residency changes (2 independent sync domains per SM fill bubbles).
template<int KP, int ACT, int WSPLIT>
__global__ __launch_bounds__(128, 2)
void mma_gemm_bf(const uint16_t* __restrict__ Ah, const uint16_t* __restrict__ Al,
                 const uint16_t* __restrict__ Bh, const uint16_t* __restrict__ Bl,
                 const float* __restrict__ bias, float* __restrict__ C,
                 uint16_t* __restrict__ Ch, uint16_t* __restrict__ Cl, int N)
{
    constexpr int LDK = 40;
    __shared__ __align__(16) uint16_t s_ah[64*LDK];
    __shared__ __align__(16) uint16_t s_al[64*LDK];
    __shared__ __align__(16) uint16_t s_bh[128*LDK];
    __shared__ __align__(16) uint16_t s_bl[128*LDK];
    __shared__ float s_bias[128];

    const int tid = threadIdx.x;
    const int wid = tid >> 5, lane = tid & 31;
    const int wm = wid & 1, wn = wid >> 1;          // 2(M) x 2(N), warp tile 32x64
    const int row0 = blockIdx.y * 64, col0 = blockIdx.x * 128;
    s_bias[tid] = bias[col0 + tid];

    const int g = lane >> 3, li = lane & 7;
    const int a_off = (wm*32 + (g&1)*8 + li) * LDK + (g>>1)*8;
    const int b_off = (wn*64 + (g>>1)*8 + li) * LDK + (g&1)*8;
    const uint32_t ah_b = smem_u32(s_ah), al_b = smem_u32(s_al);
    const uint32_t bh_b = smem_u32(s_bh), bl_b = smem_u32(s_bl);

    float acc[2][8][4];
#pragma unroll
    for (int i = 0; i < 2; i++)
#pragma unroll
        for (int j = 0; j < 8; j++)
#pragma unroll
            for (int q = 0; q < 4; q++) acc[i][j][q] = 0.f;

    // A loader: row=tid>>1 (0..63), k-half=(tid&1)*16.  B loader: row=tid, full 32k.
    const int lr = tid >> 1, lk = (tid & 1) * 16;
    const uint16_t* pAh = Ah + (size_t)(row0 + lr) * KP + lk;
    const uint16_t* pAl = Al + (size_t)(row0 + lr) * KP + lk;
    const uint16_t* pBh = Bh + (size_t)(col0 + tid) * KP;
    const uint16_t* pBl = Bl + (size_t)(col0 + tid) * KP;
    const int sA = lr * LDK + lk;
    const int sB = tid * LDK;

    uint4 ra0, ra1, rb0, rb1, rc[4], rd[4];
    ra0 = *(const uint4*)(pAh);  ra1 = *(const uint4*)(pAh + 8);
    rb0 = *(const uint4*)(pAl);  rb1 = *(const uint4*)(pAl + 8);
#pragma unroll
    for (int j = 0; j < 4; j++) {
        rc[j] = *(const uint4*)(pBh + j*8);
        rd[j] = *(const uint4*)(pBl + j*8);
    }

    for (int k0 = 0; k0 < KP; k0 += 32) {
        *(uint4*)&s_ah[sA] = ra0;  *(uint4*)&s_ah[sA + 8] = ra1;
        *(uint4*)&s_al[sA] = rb0;  *(uint4*)&s_al[sA + 8] = rb1;
#pragma unroll
        for (int j = 0; j < 4; j++) {
            *(uint4*)&s_bh[sB + j*8] = rc[j];
            *(uint4*)&s_bl[sB + j*8] = rd[j];
        }
        __syncthreads();
        if (k0 + 32 < KP) {
            ra0 = *(const uint4*)(pAh + k0 + 32);  ra1 = *(const uint4*)(pAh + k0 + 40);
            rb0 = *(const uint4*)(pAl + k0 + 32);  rb1 = *(const uint4*)(pAl + k0 + 40);
#pragma unroll
            for (int j = 0; j < 4; j++) {
                rc[j] = *(const uint4*)(pBh + k0 + 32 + j*8);
                rd[j] = *(const uint4*)(pBl + k0 + 32 + j*8);
            }
        }
#pragma unroll
        for (int s = 0; s < 2; s++) {
            const int kb = s * 16;
            uint32_t ah[2][4], al[2][4];
#pragma unroll
            for (int mt = 0; mt < 2; mt++) {
                uint32_t ao = (uint32_t)(a_off + mt*16*LDK + kb) * 2;
                ldsm4(ah[mt][0], ah[mt][1], ah[mt][2], ah[mt][3], ah_b + ao);
                ldsm4(al[mt][0], al[mt][1], al[mt][2], al[mt][3], al_b + ao);
            }
#pragma unroll
            for (int nt = 0; nt < 4; nt++) {
                uint32_t bo = (uint32_t)(b_off + nt*16*LDK + kb) * 2;
                uint32_t bh[4], bl[4];
                ldsm4(bh[0], bh[1], bh[2], bh[3], bh_b + bo);
                ldsm4(bl[0], bl[1], bl[2], bl[3], bl_b + bo);
#pragma unroll
                for (int mt = 0; mt < 2; mt++) {
#pragma unroll
                    for (int ns = 0; ns < 2; ns++) {
                        float* d = acc[mt][nt*2 + ns];
                        mma_bf16(d, ah[mt], bh[2*ns], bh[2*ns+1]);
                        mma_bf16(d, ah[mt], bl[2*ns], bl[2*ns+1]);
                        mma_bf16(d, al[mt], bh[2*ns], bh[2*ns+1]);
                    }
                }
            }
        }
        __syncthreads();
    }

    const int r_l = lane >> 2, c_l = 2 * (lane & 3);
#pragma unroll
    for (int mt = 0; mt < 2; mt++) {
#pragma unroll
        for (int n8 = 0; n8 < 8; n8++) {
            int cb = wn*64 + n8*8 + c_l;
            int col = col0 + cb;
            float b0 = s_bias[cb], b1 = s_bias[cb + 1];
            float* d = acc[mt][n8];
            int row = row0 + wm*32 + mt*16 + r_l;
            float v0 = d[0] + b0, v1 = d[1] + b1, v2 = d[2] + b0, v3 = d[3] + b1;
            if (ACT == 1) { v0=fmaxf(v0,0.f); v1=fmaxf(v1,0.f); v2=fmaxf(v2,0.f); v3=fmaxf(v3,0.f); }
            if (WSPLIT) {
                float h0 = bfr(v0), h1 = bfr(v1), h2 = bfr(v2), h3 = bfr(v3);
                *(uint32_t*)&Ch[(size_t)row * N + col]     = pack_bf2(h0, h1);
                *(uint32_t*)&Cl[(size_t)row * N + col]     = pack_bf2(v0 - h0, v1 - h1);
                *(uint32_t*)&Ch[(size_t)(row+8) * N + col] = pack_bf2(h2, h3);
                *(uint32_t*)&Cl[(size_t)(row+8) * N + col] = pack_bf2(v2 - h2, v3 - h3);
            } else {
                *(float2*)&C[(size_t)row * N + col]     = make_float2(v0, v1);
                *(float2*)&C[(size_t)(row+8) * N + col] = make_float2(v2, v3);
            }
        }
    }
}

// ======== D2 (R9 config, unchanged): occ 2, PRMT trunc split, W streamed+prefetched ========
__global__ __launch_bounds__(256, 2)
void mma_gemm_d2(const uint16_t* __restrict__ A2h, const uint16_t* __restrict__ A2l,
                 const float* __restrict__ W, const float* __restrict__ bias,
                 float* __restrict__ C)
{
    constexpr int LDK = 40;
    __shared__ __align__(16) uint16_t s_ah[32*LDK];
    __shared__ __align__(16) uint16_t s_al[32*LDK];
    __shared__ __align__(16) uint16_t s_bh[256*LDK];
    __shared__ __align__(16) uint16_t s_bl[256*LDK];
    __shared__ float s_bias[256];

    const int tid = threadIdx.x;
    const int wid = tid >> 5, lane = tid & 31;
    const int n0 = blockIdx.x * 256;
    s_bias[tid] = bias[n0 + tid];

    const int g = lane >> 3, li = lane & 7;
    const int a_off = ((g&1)*8 + li) * LDK + (g>>1)*8;
    const int b_off = (wid*32 + (g>>1)*8 + li) * LDK + (g&1)*8;
    const uint32_t ah_b = smem_u32(s_ah), al_b = smem_u32(s_al);
    const uint32_t bh_b = smem_u32(s_bh), bl_b = smem_u32(s_bl);

    float acc[2][4][4];
#pragma unroll
    for (int i = 0; i < 2; i++)
#pragma unroll
        for (int j = 0; j < 4; j++)
#pragma unroll
            for (int q = 0; q < 4; q++) acc[i][j][q] = 0.f;

    const int am = tid >> 3, akq = (tid & 7) << 2;
    const uint16_t* pa2h = A2h + am * DEC1 + akq;
    const uint16_t* pa2l = A2l + am * DEC1 + akq;
    const float* wcol = W + n0 + tid;

    float pw[32];
#pragma unroll
    for (int t = 0; t < 32; t++) pw[t] = wcol[(size_t)t * NOUT];

    for (int k0 = 0; k0 < DEC1; k0 += 32) {
        *(uint2*)&s_ah[am*LDK + akq] = *(const uint2*)(pa2h + k0);
        *(uint2*)&s_al[am*LDK + akq] = *(const uint2*)(pa2l + k0);
        {
            uint32_t wh[16], wl[16];
#pragma unroll
            for (int t = 0; t < 16; t++) {
                float a = pw[2*t], b = pw[2*t+1];
                wh[t] = hi_pair(a, b);
                wl[t] = pack_bf2(a - hi_trunc(a), b - hi_trunc(b));
            }
            int off = tid * LDK;
            *(uint4*)&s_bh[off]      = make_uint4(wh[0],wh[1],wh[2],wh[3]);
            *(uint4*)&s_bh[off + 8]  = make_uint4(wh[4],wh[5],wh[6],wh[7]);
            *(uint4*)&s_bh[off + 16] = make_uint4(wh[8],wh[9],wh[10],wh[11]);
            *(uint4*)&s_bh[off + 24] = make_uint4(wh[12],wh[13],wh[14],wh[15]);
            *(uint4*)&s_bl[off]      = make_uint4(wl[0],wl[1],wl[2],wl[3]);
            *(uint4*)&s_bl[off + 8]  = make_uint4(wl[4],wl[5],wl[6],wl[7]);
            *(uint4*)&s_bl[off + 16] = make_uint4(wl[8],wl[9],wl[10],wl[11]);
            *(uint4*)&s_bl[off + 24] = make_uint4(wl[12],wl[13],wl[14],wl[15]);
        }
        __syncthreads();
        if (k0 + 32 < DEC1) {
#pragma unroll
            for (int t = 0; t < 32; t++) pw[t] = wcol[(size_t)(k0 + 32 + t) * NOUT];
        }
#pragma unroll
        for (int s = 0; s < 2; s++) {
            const int kb = s * 16;
            uint32_t ah[2][4], al[2][4];
#pragma unroll
            for (int mt = 0; mt < 2; mt++) {
                uint32_t ao = (uint32_t)(a_off + mt*16*LDK + kb) * 2;
                ldsm4(ah[mt][0], ah[mt][1], ah[mt][2], ah[mt][3], ah_b + ao);
                ldsm4(al[mt][0], al[mt][1], al[mt][2], al[mt][3], al_b + ao);
            }
#pragma unroll
            for (int nt = 0; nt < 2; nt++) {
                uint32_t bo = (uint32_t)(b_off + nt*16*LDK + kb) * 2;
                uint32_t bh[4], bl[4];
                ldsm4(bh[0], bh[1], bh[2], bh[3], bh_b + bo);
                ldsm4(bl[0], bl[1], bl[2], bl[3], bl_b + bo);
#pragma unroll
                for (int mt = 0; mt < 2; mt++) {
#pragma unroll
                    for (int ns = 0; ns < 2; ns++) {
                        float* d = acc[mt][nt*2 + ns];
                        mma_bf16(d, ah[mt], bh[2*ns], bh[2*ns+1]);
                        mma_bf16(d, ah[mt], bl[2*ns], bl[2*ns+1]);
                        mma_bf16(d, al[mt], bh[2*ns], bh[2*ns+1]);
                    }
                }
            }
        }
        __syncthreads();
    }

    const int r_l = lane >> 2, c_l = 2 * (lane & 3);
#pragma unroll
    for (int mt = 0; mt < 2; mt++) {
#pragma unroll
        for (int n8 = 0; n8 < 4; n8++) {
            int cb = wid*32 + n8*8 + c_l;
            int col = n0 + cb;
            float b0 = s_bias[cb], b1 = s_bias[cb + 1];
            float* d = acc[mt][n8];
            int row = mt*16 + r_l;
            float v[4] = { d[0]+b0, d[1]+b1, d[2]+b0, d[3]+b1 };
#pragma unroll
            for (int q = 0; q < 4; q++) v[q] = (v[q] > 20.f) ? v[q] : log1pf(expf(v[q]));
            *(float2*)&C[(size_t)row * NOUT + col]     = make_float2(v[0], v[1]);
            *(float2*)&C[(size_t)(row+8) * NOUT + col] = make_float2(v[2], v[3]);
        }
    }
}

// ---------- scalar SGEMM (encoder head, N=32, exact fp32) ----------
template<int BM, int BN, int BK, int TM, int TN, int ACT>
__global__ void sgemm_kernel(const float* __restrict__ A, const float* __restrict__ Bw,
                             const float* __restrict__ bias, float* __restrict__ C,
                             int M, int N, int K)
{
    constexpr int TX = BN / TN, TY = BM / TM, NTH = TX * TY, LDA = BM + 4;
    __shared__ float As[BK * LDA];
    __shared__ float Bs[BK * BN];
    const int tid = threadIdx.x, tx = tid % TX, ty = tid / TX;
    const int row0 = blockIdx.y * BM, col0 = blockIdx.x * BN;

    float acc[TM][TN];
#pragma unroll
    for (int i = 0; i < TM; i++)
#pragma unroll
        for (int j = 0; j < TN; j++) acc[i][j] = 0.f;

    for (int k0 = 0; k0 < K; k0 += BK) {
        for (int i = tid; i < BM * BK; i += NTH) {
            int m = i / BK, kk = i % BK, kg = k0 + kk;
            As[kk * LDA + m] = (kg < K) ? A[(size_t)(row0 + m) * K + kg] : 0.f;
        }
        for (int i = tid; i < BK * BN; i += NTH) {
            int kk = i / BN, n = i % BN, kg = k0 + kk;
            Bs[kk * BN + n] = (kg < K) ? Bw[(size_t)kg * N + col0 + n] : 0.f;
        }
        __syncthreads();
#pragma unroll
        for (int kk = 0; kk < BK; kk++) {
            float a[TM], b[TN];
#pragma unroll
            for (int i = 0; i < TM; i++) a[i] = As[kk * LDA + ty * TM + i];
#pragma unroll
            for (int j = 0; j < TN; j++) b[j] = Bs[kk * BN + tx * TN + j];
#pragma unroll
            for (int i = 0; i < TM; i++)
#pragma unroll
                for (int j = 0; j < TN; j++) acc[i][j] = fmaf(a[i], b[j], acc[i][j]);
        }
        __syncthreads();
    }
#pragma unroll
    for (int i = 0; i < TM; i++) {
        int r = row0 + ty * TM + i;
#pragma unroll
        for (int j = 0; j < TN; j++) {
            int c = col0 + tx * TN + j;
            float v = acc[i][j] + bias[c];
            if (ACT) v = fmaxf(v, 0.f);
            C[(size_t)r * N + c] = v;
        }
    }
}

__global__ void reparam_kernel(const float* __restrict__ enc, const float* __restrict__ eps,
                               float* __restrict__ om, float* __restrict__ olv,
                               float* __restrict__ ze)
{
    int idx = blockIdx.x * 256 + threadIdx.x;
    if (idx >= MM * DD) return;
    int row = idx >> 4, d = idx & 15;
    float m = enc[row * E2 + d], lv = enc[row * E2 + DD + d];
    om[idx] = m; olv[idx] = lv;
    ze[idx] = fmaf(expf(0.5f * lv), eps[idx], m);
}

__global__ void vq_kernel(const float* __restrict__ ze, const float* __restrict__ cb,
                          float* __restrict__ zq, float* __restrict__ part)
{
    __shared__ float s_cb[256 * DD];
    __shared__ float s_csq[256];
    __shared__ float s_red[128];
    const int row = blockIdx.x * 128 + threadIdx.x;
    float z[DD];
#pragma unroll
    for (int d = 0; d < DD; d++) z[d] = ze[row * DD + d];

    float best = 3.4e38f; int bi = 0;
    for (int t = 0; t < KCB; t += 256) {
        __syncthreads();
        for (int i = threadIdx.x; i < 256 * DD; i += 128) s_cb[i] = cb[t * DD + i];
        __syncthreads();
        for (int kc = threadIdx.x; kc < 256; kc += 128) {
            float cs = 0.f;
#pragma unroll
            for (int d = 0; d < DD; d++) { float c = s_cb[kc * DD + d]; cs = fmaf(c, c, cs); }
            s_csq[kc] = cs;
        }
        __syncthreads();
#pragma unroll 2
        for (int k = 0; k < 256; k++) {
            float dot = 0.f;
#pragma unroll
            for (int d = 0; d < DD; d++) dot = fmaf(z[d], s_cb[k * DD + d], dot);
            float score = s_csq[k] - 2.f * dot;
            if (score < best) { best = score; bi = t + k; }
        }
    }
    float loss = 0.f;
#pragma unroll
    for (int d = 0; d < DD; d++) {
        float q = cb[bi * DD + d];
        zq[row * DD + d] = q;
        float df = z[d] - q;
        loss = fmaf(df, df, loss);
    }
    s_red[threadIdx.x] = loss;
    __syncthreads();
    for (int s = 64; s > 0; s >>= 1) {
        if (threadIdx.x < s) s_red[threadIdx.x] += s_red[threadIdx.x + s];
        __syncthreads();
    }
    if (threadIdx.x == 0) part[blockIdx.x] = s_red[0];
}

__global__ void vq_reduce_kernel(const float* __restrict__ part, float* __restrict__ out)
{
    if (threadIdx.x == 0) {
        float t = 0.f;
        for (int i = 0; i < NVQBLK; i++) t += part[i];
        out[0] = t / (float)(MM * DD);
    }
}

template<int KTILE>
__global__ void skinny_splitk_kernel(const float* __restrict__ Z, const float* __restrict__ W,
                                     float* __restrict__ C, int K, int N, int kchunk)
{
    const int j = blockIdx.x * 128 + threadIdx.x;
    const int k0 = blockIdx.y * kchunk;
    const int kend = min(k0 + kchunk, K);
    __shared__ float s_z[BB * KTILE];
    float acc[BB];
#pragma unroll
    for (int b = 0; b < BB; b++) acc[b] = 0.f;
    for (int kt = k0; kt < kend; kt += KTILE) {
        __syncthreads();
        for (int i = threadIdx.x; i < BB * KTILE; i += 128) {
            int b = i / KTILE, kk = i % KTILE;
            s_z[i] = Z[(size_t)b * K + kt + kk];
        }
        __syncthreads();
        for (int kk = 0; kk < KTILE; kk += 4) {
            float w0 = W[(size_t)(kt + kk + 0) * N + j];
            float w1 = W[(size_t)(kt + kk + 1) * N + j];
            float w2 = W[(size_t)(kt + kk + 2) * N + j];
            float w3 = W[(size_t)(kt + kk + 3) * N + j];
#pragma unroll
            for (int b = 0; b < BB; b++) {
                float4 zz = *(const float4*)&s_z[b * KTILE + kk];
                acc[b] = fmaf(zz.x, w0, acc[b]);
                acc[b] = fmaf(zz.y, w1, acc[b]);
                acc[b] = fmaf(zz.z, w2, acc[b]);
                acc[b] = fmaf(zz.w, w3, acc[b]);
            }
        }
    }
#pragma unroll
    for (int b = 0; b < BB; b++) atomicAdd(&C[b * N + j], acc[b]);
}

__global__ void zero_kernel(float* __restrict__ p, int n)
{
    int i = blockIdx.x * 256 + threadIdx.x;
    if (i < n) p[i] = 0.f;
}
__global__ void bias_relu_kernel(float* __restrict__ C, const float* __restrict__ bias,
                                 int N, int total)
{
    int i = blockIdx.x * 256 + threadIdx.x;
    if (i < total) { float v = C[i] + bias[i % N]; C[i] = fmaxf(v, 0.f); }
}

extern "C" void kernel_launch(void* const* d_in, const int* in_sizes, int n_in,
                              void* d_out, int out_size)
{
    const float* x   = (const float*)d_in[0];
    const float* eps = (const float*)d_in[1];
    const float* ew0 = (const float*)d_in[2];
    const float* eb0 = (const float*)d_in[3];
    const float* ew1 = (const float*)d_in[4];
    const float* eb1 = (const float*)d_in[5];
    const float* ew2 = (const float*)d_in[6];
    const float* eb2 = (const float*)d_in[7];
    const float* dw0 = (const float*)d_in[8];
    const float* db0 = (const float*)d_in[9];
    const float* dw1 = (const float*)d_in[10];
    const float* db1 = (const float*)d_in[11];
    const float* dw2 = (const float*)d_in[12];
    const float* db2 = (const float*)d_in[13];
    const float* cb  = (const float*)d_in[14];
    float* out = (float*)d_out;

    uint16_t *p_xh, *p_xl, *p_w0h, *p_w0l, *p_w1h, *p_w1l, *p_h0h, *p_h0l, *p_a2h, *p_a2l;
    float *p_h1, *p_enc, *p_ze, *p_zq, *p_hd0, *p_hd1, *p_vq;
    cudaGetSymbolAddress((void**)&p_xh,  g_xh);
    cudaGetSymbolAddress((void**)&p_xl,  g_xl);
    cudaGetSymbolAddress((void**)&p_w0h, g_w0h);
    cudaGetSymbolAddress((void**)&p_w0l, g_w0l);
    cudaGetSymbolAddress((void**)&p_w1h, g_w1h);
    cudaGetSymbolAddress((void**)&p_w1l, g_w1l);
    cudaGetSymbolAddress((void**)&p_h0h, g_h0h);
    cudaGetSymbolAddress((void**)&p_h0l, g_h0l);
    cudaGetSymbolAddress((void**)&p_a2h, g_a2h);
    cudaGetSymbolAddress((void**)&p_a2l, g_a2l);
    cudaGetSymbolAddress((void**)&p_h1,  g_h1);
    cudaGetSymbolAddress((void**)&p_enc, g_enc);
    cudaGetSymbolAddress((void**)&p_ze,  g_ze);
    cudaGetSymbolAddress((void**)&p_zq,  g_zq);
    cudaGetSymbolAddress((void**)&p_hd0, g_hd0);
    cudaGetSymbolAddress((void**)&p_hd1, g_hd1);
    cudaGetSymbolAddress((void**)&p_vq,  g_vqpart);

    // pre-split inputs/weights
    split_rm<<<(MM*KP0 + 255)/256, 256>>>(x, p_xh, p_xl, FFE, KP0, MM*KP0);
    split_tr<<<(E0*KP0 + 255)/256, 256>>>(ew0, p_w0h, p_w0l, FFE, E0, KP0, E0*KP0);
    split_tr<<<(E1*E0 + 255)/256, 256>>>(ew1, p_w1h, p_w1l, E0, E1, E0, E1*E0);

    // encoder L0: writes split bf16 h0 directly  (BM=64, occ 2)
    mma_gemm_bf<KP0, 1, 1><<<dim3(E0/128, MM/64), 128>>>(
        p_xh, p_xl, p_w0h, p_w0l, eb0, nullptr, p_h0h, p_h0l, E0);
    // encoder L1
    mma_gemm_bf<E0, 1, 0><<<dim3(E1/128, MM/64), 128>>>(
        p_h0h, p_h0l, p_w1h, p_w1l, eb1, p_h1, nullptr, nullptr, E1);
    // encoder head (exact fp32)
    sgemm_kernel<128,32,16,8,4,0><<<dim3(1, MM/128), 128>>>(p_h1, ew2, eb2, p_enc, MM, E2, E1);

    reparam_kernel<<<(MM*DD + 255)/256, 256>>>(p_enc, eps, out + MEAN_OFF, out + LV_OFF, p_ze);

    vq_kernel<<<NVQBLK, 128>>>(p_ze, cb, p_zq, p_vq);
    vq_reduce_kernel<<<1, 32>>>(p_vq, out + VQ_OFF);

    // decoder D0 / D1: exact fp32 split-K
    zero_kernel<<<(BB*DEC0 + 255)/256, 256>>>(p_hd0, BB*DEC0);
    skinny_splitk_kernel<64><<<dim3(DEC0/128, 16), 128>>>(p_zq, dw0, p_hd0, ZFD, DEC0, 576);
    bias_relu_kernel<<<(BB*DEC0 + 255)/256, 256>>>(p_hd0, db0, DEC0, BB*DEC0);

    zero_kernel<<<(BB*DEC1 + 255)/256, 256>>>(p_hd1, BB*DEC1);
    skinny_splitk_kernel<64><<<dim3(DEC1/128, 8), 128>>>(p_hd0, dw1, p_hd1, DEC0, DEC1, 128);
    bias_relu_kernel<<<(BB*DEC1 + 255)/256, 256>>>(p_hd1, db1, DEC1, BB*DEC1);

    // decoder D2
    split_rm<<<(BB*DEC1 + 255)/256, 256>>>(p_hd1, p_a2h, p_a2l, DEC1, DEC1, BB*DEC1);
    mma_gemm_d2<<<NOUT/256, 256>>>(p_a2h, p_a2l, dw2, db2, out + REC_OFF);
}

// round 15
// speedup vs baseline: 1.1363x; 1.1363x over previous
#include <cuda_runtime.h>
#include <cuda_bf16.h>
#include <math.h>
#include <stdint.h>

#define BB   32
#define SS   576
#define FFE  700
#define KP0  704
#define DD   16
#define KCB  1024
#define MM   (BB*SS)
#define E0   512
#define E1   256
#define E2   32
#define DEC0 1024
#define DEC1 512
#define NOUT (SS*FFE)
#define ZFD  (SS*DD)

#define REC_OFF  0
#define MEAN_OFF (BB*NOUT)
#define LV_OFF   (MEAN_OFF + MM*DD)
#define VQ_OFF   (LV_OFF + MM*DD)
#define NVQBLK   144

// ---------------- scratch (device globals) ----------------
// x and h0 stored in mma-fragment-major layout (uint32 per lane/reg per 16x16 tile)
__device__ uint16_t g_xh[MM*KP0],  g_xl[MM*KP0];
__device__ uint16_t g_w0h[E0*KP0], g_w0l[E0*KP0];
__device__ uint16_t g_w1h[E1*E0],  g_w1l[E1*E0];
__device__ uint16_t g_h0h[MM*E0],  g_h0l[MM*E0];
__device__ uint16_t g_a2h[BB*DEC1], g_a2l[BB*DEC1];
__device__ float g_h1[MM*E1];
__device__ float g_enc[MM*E2];
__device__ float g_ze[MM*DD];
__device__ float g_zq[MM*DD];
__device__ float g_hd0[BB*DEC0];
__device__ float g_hd1[BB*DEC1];
__device__ float g_vqpart[NVQBLK];

// ---------------- helpers ----------------
__device__ __forceinline__ uint32_t smem_u32(const void* p) {
    uint32_t a;
    asm("{ .reg .u64 t; cvta.to.shared.u64 t, %1; cvt.u32.u64 %0, t; }" : "=r"(a) : "l"(p));
    return a;
}
__device__ __forceinline__ void ldsm4(uint32_t& r0, uint32_t& r1, uint32_t& r2, uint32_t& r3, uint32_t addr) {
    asm volatile("ldmatrix.sync.aligned.m8n8.x4.shared.b16 {%0,%1,%2,%3}, [%4];"
        : "=r"(r0), "=r"(r1), "=r"(r2), "=r"(r3) : "r"(addr));
}
__device__ __forceinline__ void mma_bf16(float* d, const uint32_t* a, uint32_t b0, uint32_t b1) {
    asm volatile("mma.sync.aligned.m16n8k16.row.col.f32.bf16.bf16.f32 "
        "{%0,%1,%2,%3}, {%4,%5,%6,%7}, {%8,%9}, {%0,%1,%2,%3};"
        : "+f"(d[0]), "+f"(d[1]), "+f"(d[2]), "+f"(d[3])
        : "r"(a[0]), "r"(a[1]), "r"(a[2]), "r"(a[3]), "r"(b0), "r"(b1));
}
__device__ __forceinline__ uint32_t pack_bf2(float a, float b) {
    __nv_bfloat162 t = __floats2bfloat162_rn(a, b);
    return *(uint32_t*)&t;
}
__device__ __forceinline__ float bfr(float v) {
    return __bfloat162float(__float2bfloat16(v));
}
__device__ __forceinline__ uint32_t hi_pair(float a, float b) {
    uint32_t r;
    asm("prmt.b32 %0, %1, %2, 0x7632;" : "=r"(r) : "r"(__float_as_uint(a)), "r"(__float_as_uint(b)));
    return r;
}
__device__ __forceinline__ float hi_trunc(float v) {
    return __uint_as_float(__float_as_uint(v) & 0xFFFF0000u);
}

// fragment-layout address (in uint32 units) of the pair (m,k),(m,k+1), k even
__device__ __forceinline__ size_t frag_addr(int m, int k, int K16) {
    int tm = m >> 4, tk = k >> 4;
    int lane = ((m & 7) << 2) + ((k & 7) >> 1);
    int reg  = ((m >> 3) & 1) + (((k >> 3) & 1) << 1);
    return ((size_t)(tm * K16 + tk) << 7) + (lane << 2) + reg;
}

// ---------------- pre-split kernels ----------------
// row-major split (used for D2's A)
__global__ void split_rm(const float* __restrict__ src, uint16_t* __restrict__ hi,
                         uint16_t* __restrict__ lo, int K, int Kpad, int total)
{
    int i = blockIdx.x * 256 + threadIdx.x;
    if (i >= total) return;
    int r = i / Kpad, c = i % Kpad;
    float v = (c < K) ? src[(size_t)r * K + c] : 0.f;
    float h = bfr(v);
    __nv_bfloat16 hb = __float2bfloat16(h);
    __nv_bfloat16 lb = __float2bfloat16(v - h);
    hi[i] = *(uint16_t*)&hb;
    lo[i] = *(uint16_t*)&lb;
}
// fragment-major split (A operand for tensor GEMMs)
__global__ void split_frag(const float* __restrict__ src, uint16_t* __restrict__ hi,
                           uint16_t* __restrict__ lo, int K, int Kpad, int totalU32)
{
    int i = blockIdx.x * 256 + threadIdx.x;
    if (i >= totalU32) return;
    int tile = i >> 7, rem = i & 127;
    int lane = rem >> 2, reg = rem & 3;
    int K16 = Kpad >> 4;
    int tm = tile / K16, tk = tile - tm * K16;
    int m = tm * 16 + (lane >> 2) + ((reg & 1) << 3);
    int k = tk * 16 + ((lane & 3) << 1) + ((reg >> 1) << 3);
    float v0 = (k     < K) ? src[(size_t)m * K + k]     : 0.f;
    float v1 = (k + 1 < K) ? src[(size_t)m * K + k + 1] : 0.f;
    float h0 = bfr(v0), h1 = bfr(v1);
    ((uint32_t*)hi)[i] = pack_bf2(h0, h1);
    ((uint32_t*)lo)[i] = pack_bf2(v0 - h0, v1 - h1);
}
// transposed split (B operand: [K][N] -> [N][Kpad])
__global__ void split_tr(const float* __restrict__ src, uint16_t* __restrict__ hi,
                         uint16_t* __restrict__ lo, int K, int N, int Kpad, int total)
{
    int i = blockIdx.x * 256 + threadIdx.x;
    if (i >= total) return;
    int n = i / Kpad, k = i % Kpad;
    float v = (k < K) ? src[(size_t)k * N + n] : 0.f;
    float h = bfr(v);
    __nv_bfloat16 hb = __float2bfloat16(h);
    __nv_bfloat16 lb = __float2bfloat16(v - h);
    hi[i] = *(uint16_t*)&hb;
    lo[i] = *(uint16_t*)&lb;
}

// ======== MMA GEMM v4: R8 geometry (BM=128 BN=128 BK=32, 4Mx2N warps), A direct-from-frag ========
// A arrives in fragment-major layout via LDG.128 (no smem); B via smem + ldsm as before.
// WSPLIT: epilogue scatters split output into fragment layout for the next GEMM's A.
template<int KP, int ACT, int WSPLIT>
__global__ __launch_bounds__(256, 1)
void mma_gemm_bf(const uint16_t* __restrict__ Ah, const uint16_t* __restrict__ Al,
                 const uint16_t* __restrict__ Bh, const uint16_t* __restrict__ Bl,
                 const float* __restrict__ bias, float* __restrict__ C,
                 uint16_t* __restrict__ Ch, uint16_t* __restrict__ Cl, int N)
{
    constexpr int LDK = 40;
    constexpr int K16 = KP / 16;
    constexpr int NCH = KP / 32;
    __shared__ __align__(16) uint16_t s_bh[128*LDK];
    __shared__ __align__(16) uint16_t s_bl[128*LDK];
    __shared__ float s_bias[128];

    const int tid = threadIdx.x;
    const int wid = tid >> 5, lane = tid & 31;
    const int wm = wid & 3, wn = wid >> 2;          // 4(M) x 2(N), warp tile 32x64
    const int row0 = blockIdx.y * 128, col0 = blockIdx.x * 128;
    if (tid < 128) s_bias[tid] = bias[col0 + tid];

    const int g = lane >> 3, li = lane & 7;
    const int b_off = (wn*64 + (g>>1)*8 + li) * LDK + (g&1)*8;
    const uint32_t bh_b = smem_u32(s_bh), bl_b = smem_u32(s_bl);

    float acc[2][8][4];
#pragma unroll
    for (int i = 0; i < 2; i++)
#pragma unroll
        for (int j = 0; j < 8; j++)
#pragma unroll
            for (int q = 0; q < 4; q++) acc[i][j][q] = 0.f;

    // ---- A: direct fragment loads ----
    const int tm0 = (row0 + wm * 32) >> 4;          // first 16-row tile of this warp
    const uint4* fAh = (const uint4*)Ah;            // tile = 32 uint4; lane-indexed
    const uint4* fAl = (const uint4*)Al;
    uint4 Ab[2][8];                                  // [buf][(mt*2+s)*2+hl]

    // ---- B loader (R8): row=tid>>1, k-half=(tid&1)*16 ----
    const int lr = tid >> 1, lk = (tid & 1) * 16;
    const uint16_t* pBh = Bh + (size_t)(col0 + lr) * KP + lk;
    const uint16_t* pBl = Bl + (size_t)(col0 + lr) * KP + lk;
    const int sB = lr * LDK + lk;

    uint4 rc0, rc1, rd0, rd1;
    rc0 = *(const uint4*)(pBh);  rc1 = *(const uint4*)(pBh + 8);
    rd0 = *(const uint4*)(pBl);  rd1 = *(const uint4*)(pBl + 8);
#pragma unroll
    for (int mt = 0; mt < 2; mt++)
#pragma unroll
        for (int s = 0; s < 2; s++) {
            int t = (tm0 + mt) * K16 + s;
            Ab[0][(mt*2+s)*2+0] = fAh[t*32 + lane];
            Ab[0][(mt*2+s)*2+1] = fAl[t*32 + lane];
        }

#pragma unroll 2
    for (int c = 0; c < NCH; c++) {
        *(uint4*)&s_bh[sB] = rc0;  *(uint4*)&s_bh[sB + 8] = rc1;
        *(uint4*)&s_bl[sB] = rd0;  *(uint4*)&s_bl[sB + 8] = rd1;
        __syncthreads();
        if (c + 1 < NCH) {
            rc0 = *(const uint4*)(pBh + (c+1)*32);  rc1 = *(const uint4*)(pBh + (c+1)*32 + 8);
            rd0 = *(const uint4*)(pBl + (c+1)*32);  rd1 = *(const uint4*)(pBl + (c+1)*32 + 8);
#pragma unroll
            for (int mt = 0; mt < 2; mt++)
#pragma unroll
                for (int s = 0; s < 2; s++) {
                    int t = (tm0 + mt) * K16 + 2*(c+1) + s;
                    Ab[(c+1)&1][(mt*2+s)*2+0] = fAh[t*32 + lane];
                    Ab[(c+1)&1][(mt*2+s)*2+1] = fAl[t*32 + lane];
                }
        }
#pragma unroll
        for (int s = 0; s < 2; s++) {
            const int kb = s * 16;
#pragma unroll
            for (int nt = 0; nt < 4; nt++) {
                uint32_t bo = (uint32_t)(b_off + nt*16*LDK + kb) * 2;
                uint32_t bh[4], bl[4];
                ldsm4(bh[0], bh[1], bh[2], bh[3], bh_b + bo);
                ldsm4(bl[0], bl[1], bl[2], bl[3], bl_b + bo);
#pragma unroll
                for (int mt = 0; mt < 2; mt++) {
                    const uint32_t* ah = (const uint32_t*)&Ab[c&1][(mt*2+s)*2+0];
                    const uint32_t* al = (const uint32_t*)&Ab[c&1][(mt*2+s)*2+1];
#pragma unroll
                    for (int ns = 0; ns < 2; ns++) {
                        float* d = acc[mt][nt*2 + ns];
                        mma_bf16(d, ah, bh[2*ns], bh[2*ns+1]);
                        mma_bf16(d, ah, bl[2*ns], bl[2*ns+1]);
                        mma_bf16(d, al, bh[2*ns], bh[2*ns+1]);
                    }
                }
            }
        }
        __syncthreads();
    }

    const int r_l = lane >> 2, c_l = 2 * (lane & 3);
    const int K16n = N >> 4;
#pragma unroll
    for (int mt = 0; mt < 2; mt++) {
#pragma unroll
        for (int n8 = 0; n8 < 8; n8++) {
            int cb = wn*64 + n8*8 + c_l;
            int col = col0 + cb;
            float b0 = s_bias[cb], b1 = s_bias[cb + 1];
            float* d = acc[mt][n8];
            int row = row0 + wm*32 + mt*16 + r_l;
            float v0 = d[0] + b0, v1 = d[1] + b1, v2 = d[2] + b0, v3 = d[3] + b1;
            if (ACT == 1) { v0=fmaxf(v0,0.f); v1=fmaxf(v1,0.f); v2=fmaxf(v2,0.f); v3=fmaxf(v3,0.f); }
            if (WSPLIT) {
                // scatter into fragment layout for next GEMM's A operand
                float h0 = bfr(v0), h1 = bfr(v1), h2 = bfr(v2), h3 = bfr(v3);
                size_t a0 = frag_addr(row,     col, K16n);
                size_t a1 = frag_addr(row + 8, col, K16n);
                ((uint32_t*)Ch)[a0] = pack_bf2(h0, h1);
                ((uint32_t*)Cl)[a0] = pack_bf2(v0 - h0, v1 - h1);
                ((uint32_t*)Ch)[a1] = pack_bf2(h2, h3);
                ((uint32_t*)Cl)[a1] = pack_bf2(v2 - h2, v3 - h3);
            } else {
                *(float2*)&C[(size_t)row * N + col]     = make_float2(v0, v1);
                *(float2*)&C[(size_t)(row+8) * N + col] = make_float2(v2, v3);
            }
        }
    }
}

// ======== D2 (unchanged from 711us version): occ 2, PRMT trunc split ========
__global__ __launch_bounds__(256, 2)
void mma_gemm_d2(const uint16_t* __restrict__ A2h, const uint16_t* __restrict__ A2l,
                 const float* __restrict__ W, const float* __restrict__ bias,
                 float* __restrict__ C)
{
    constexpr int LDK = 40;
    __shared__ __align__(16) uint16_t s_ah[32*LDK];
    __shared__ __align__(16) uint16_t s_al[32*LDK];
    __shared__ __align__(16) uint16_t s_bh[256*LDK];
    __shared__ __align__(16) uint16_t s_bl[256*LDK];
    __shared__ float s_bias[256];

    const int tid = threadIdx.x;
    const int wid = tid >> 5, lane = tid & 31;
    const int n0 = blockIdx.x * 256;
    s_bias[tid] = bias[n0 + tid];

    const int g = lane >> 3, li = lane & 7;
    const int a_off = ((g&1)*8 + li) * LDK + (g>>1)*8;
    const int b_off = (wid*32 + (g>>1)*8 + li) * LDK + (g&1)*8;
    const uint32_t ah_b = smem_u32(s_ah), al_b = smem_u32(s_al);
    const uint32_t bh_b = smem_u32(s_bh), bl_b = smem_u32(s_bl);

    float acc[2][4][4];
#pragma unroll
    for (int i = 0; i < 2; i++)
#pragma unroll
        for (int j = 0; j < 4; j++)
#pragma unroll
            for (int q = 0; q < 4; q++) acc[i][j][q] = 0.f;

    const int am = tid >> 3, akq = (tid & 7) << 2;
    const uint16_t* pa2h = A2h + am * DEC1 + akq;
    const uint16_t* pa2l = A2l + am * DEC1 + akq;
    const float* wcol = W + n0 + tid;

    float pw[32];
#pragma unroll
    for (int t = 0; t < 32; t++) pw[t] = wcol[(size_t)t * NOUT];

    for (int k0 = 0; k0 < DEC1; k0 += 32) {
        *(uint2*)&s_ah[am*LDK + akq] = *(const uint2*)(pa2h + k0);
        *(uint2*)&s_al[am*LDK + akq] = *(const uint2*)(pa2l + k0);
        {
            uint32_t wh[16], wl[16];
#pragma unroll
            for (int t = 0; t < 16; t++) {
                float a = pw[2*t], b = pw[2*t+1];
                wh[t] = hi_pair(a, b);
                wl[t] = pack_bf2(a - hi_trunc(a), b - hi_trunc(b));
            }
            int off = tid * LDK;
            *(uint4*)&s_bh[off]      = make_uint4(wh[0],wh[1],wh[2],wh[3]);
            *(uint4*)&s_bh[off + 8]  = make_uint4(wh[4],wh[5],wh[6],wh[7]);
            *(uint4*)&s_bh[off + 16] = make_uint4(wh[8],wh[9],wh[10],wh[11]);
            *(uint4*)&s_bh[off + 24] = make_uint4(wh[12],wh[13],wh[14],wh[15]);
            *(uint4*)&s_bl[off]      = make_uint4(wl[0],wl[1],wl[2],wl[3]);
            *(uint4*)&s_bl[off + 8]  = make_uint4(wl[4],wl[5],wl[6],wl[7]);
            *(uint4*)&s_bl[off + 16] = make_uint4(wl[8],wl[9],wl[10],wl[11]);
            *(uint4*)&s_bl[off + 24] = make_uint4(wl[12],wl[13],wl[14],wl[15]);
        }
        __syncthreads();
        if (k0 + 32 < DEC1) {
#pragma unroll
            for (int t = 0; t < 32; t++) pw[t] = wcol[(size_t)(k0 + 32 + t) * NOUT];
        }
#pragma unroll
        for (int s = 0; s < 2; s++) {
            const int kb = s * 16;
            uint32_t ah[2][4], al[2][4];
#pragma unroll
            for (int mt = 0; mt < 2; mt++) {
                uint32_t ao = (uint32_t)(a_off + mt*16*LDK + kb) * 2;
                ldsm4(ah[mt][0], ah[mt][1], ah[mt][2], ah[mt][3], ah_b + ao);
                ldsm4(al[mt][0], al[mt][1], al[mt][2], al[mt][3], al_b + ao);
            }
#pragma unroll
            for (int nt = 0; nt < 2; nt++) {
                uint32_t bo = (uint32_t)(b_off + nt*16*LDK + kb) * 2;
                uint32_t bh[4], bl[4];
                ldsm4(bh[0], bh[1], bh[2], bh[3], bh_b + bo);
                ldsm4(bl[0], bl[1], bl[2], bl[3], bl_b + bo);
#pragma unroll
                for (int mt = 0; mt < 2; mt++) {
#pragma unroll
                    for (int ns = 0; ns < 2; ns++) {
                        float* d = acc[mt][nt*2 + ns];
                        mma_bf16(d, ah[mt], bh[2*ns], bh[2*ns+1]);
                        mma_bf16(d, ah[mt], bl[2*ns], bl[2*ns+1]);
                        mma_bf16(d, al[mt], bh[2*ns], bh[2*ns+1]);
                    }
                }
            }
        }
        __syncthreads();
    }

    const int r_l = lane >> 2, c_l = 2 * (lane & 3);
#pragma unroll
    for (int mt = 0; mt < 2; mt++) {
#pragma unroll
        for (int n8 = 0; n8 < 4; n8++) {
            int cb = wid*32 + n8*8 + c_l;
            int col = n0 + cb;
            float b0 = s_bias[cb], b1 = s_bias[cb + 1];
            float* d = acc[mt][n8];
            int row = mt*16 + r_l;
            float v[4] = { d[0]+b0, d[1]+b1, d[2]+b0, d[3]+b1 };
#pragma unroll
            for (int q = 0; q < 4; q++) v[q] = (v[q] > 20.f) ? v[q] : log1pf(expf(v[q]));
            *(float2*)&C[(size_t)row * NOUT + col]     = make_float2(v[0], v[1]);
            *(float2*)&C[(size_t)(row+8) * NOUT + col] = make_float2(v[2], v[3]);
        }
    }
}

// ---------- scalar SGEMM (encoder head, N=32, exact fp32) ----------
template<int BM, int BN, int BK, int TM, int TN, int ACT>
__global__ void sgemm_kernel(const float* __restrict__ A, const float* __restrict__ Bw,
                             const float* __restrict__ bias, float* __restrict__ C,
                             int M, int N, int K)
{
    constexpr int TX = BN / TN, TY = BM / TM, NTH = TX * TY, LDA = BM + 4;
    __shared__ float As[BK * LDA];
    __shared__ float Bs[BK * BN];
    const int tid = threadIdx.x, tx = tid % TX, ty = tid / TX;
    const int row0 = blockIdx.y * BM, col0 = blockIdx.x * BN;

    float acc[TM][TN];
#pragma unroll
    for (int i = 0; i < TM; i++)
#pragma unroll
        for (int j = 0; j < TN; j++) acc[i][j] = 0.f;

    for (int k0 = 0; k0 < K; k0 += BK) {
        for (int i = tid; i < BM * BK; i += NTH) {
            int m = i / BK, kk = i % BK, kg = k0 + kk;
            As[kk * LDA + m] = (kg < K) ? A[(size_t)(row0 + m) * K + kg] : 0.f;
        }
        for (int i = tid; i < BK * BN; i += NTH) {
            int kk = i / BN, n = i % BN, kg = k0 + kk;
            Bs[kk * BN + n] = (kg < K) ? Bw[(size_t)kg * N + col0 + n] : 0.f;
        }
        __syncthreads();
#pragma unroll
        for (int kk = 0; kk < BK; kk++) {
            float a[TM], b[TN];
#pragma unroll
            for (int i = 0; i < TM; i++) a[i] = As[kk * LDA + ty * TM + i];
#pragma unroll
            for (int j = 0; j < TN; j++) b[j] = Bs[kk * BN + tx * TN + j];
#pragma unroll
            for (int i = 0; i < TM; i++)
#pragma unroll
                for (int j = 0; j < TN; j++) acc[i][j] = fmaf(a[i], b[j], acc[i][j]);
        }
        __syncthreads();
    }
#pragma unroll
    for (int i = 0; i < TM; i++) {
        int r = row0 + ty * TM + i;
#pragma unroll
        for (int j = 0; j < TN; j++) {
            int c = col0 + tx * TN + j;
            float v = acc[i][j] + bias[c];
            if (ACT) v = fmaxf(v, 0.f);
            C[(size_t)r * N + c] = v;
        }
    }
}

__global__ void reparam_kernel(const float* __restrict__ enc, const float* __restrict__ eps,
                               float* __restrict__ om, float* __restrict__ olv,
                               float* __restrict__ ze)
{
    int idx = blockIdx.x * 256 + threadIdx.x;
    if (idx >= MM * DD) return;
    int row = idx >> 4, d = idx & 15;
    float m = enc[row * E2 + d], lv = enc[row * E2 + DD + d];
    om[idx] = m; olv[idx] = lv;
    ze[idx] = fmaf(expf(0.5f * lv), eps[idx], m);
}

__global__ void vq_kernel(const float* __restrict__ ze, const float* __restrict__ cb,
                          float* __restrict__ zq, float* __restrict__ part)
{
    __shared__ float s_cb[256 * DD];
    __shared__ float s_csq[256];
    __shared__ float s_red[128];
    const int row = blockIdx.x * 128 + threadIdx.x;
    float z[DD];
#pragma unroll
    for (int d = 0; d < DD; d++) z[d] = ze[row * DD + d];

    float best = 3.4e38f; int bi = 0;
    for (int t = 0; t < KCB; t += 256) {
        __syncthreads();
        for (int i = threadIdx.x; i < 256 * DD; i += 128) s_cb[i] = cb[t * DD + i];
        __syncthreads();
        for (int kc = threadIdx.x; kc < 256; kc += 128) {
            float cs = 0.f;
#pragma unroll
            for (int d = 0; d < DD; d++) { float c = s_cb[kc * DD + d]; cs = fmaf(c, c, cs); }
            s_csq[kc] = cs;
        }
        __syncthreads();
#pragma unroll 2
        for (int k = 0; k < 256; k++) {
            float dot = 0.f;
#pragma unroll
            for (int d = 0; d < DD; d++) dot = fmaf(z[d], s_cb[k * DD + d], dot);
            float score = s_csq[k] - 2.f * dot;
            if (score < best) { best = score; bi = t + k; }
        }
    }
    float loss = 0.f;
#pragma unroll
    for (int d = 0; d < DD; d++) {
        float q = cb[bi * DD + d];
        zq[row * DD + d] = q;
        float df = z[d] - q;
        loss = fmaf(df, df, loss);
    }
    s_red[threadIdx.x] = loss;
    __syncthreads();
    for (int s = 64; s > 0; s >>= 1) {
        if (threadIdx.x < s) s_red[threadIdx.x] += s_red[threadIdx.x + s];
        __syncthreads();
    }
    if (threadIdx.x == 0) part[blockIdx.x] = s_red[0];
}

__global__ void vq_reduce_kernel(const float* __restrict__ part, float* __restrict__ out)
{
    if (threadIdx.x == 0) {
        float t = 0.f;
        for (int i = 0; i < NVQBLK; i++) t += part[i];
        out[0] = t / (float)(MM * DD);
    }
}

template<int KTILE>
__global__ void skinny_splitk_kernel(const float* __restrict__ Z, const float* __restrict__ W,
                                     float* __restrict__ C, int K, int N, int kchunk)
{
    const int j = blockIdx.x * 128 + threadIdx.x;
    const int k0 = blockIdx.y * kchunk;
    const int kend = min(k0 + kchunk, K);
    __shared__ float s_z[BB * KTILE];
    float acc[BB];
#pragma unroll
    for (int b = 0; b < BB; b++) acc[b] = 0.f;
    for (int kt = k0; kt < kend; kt += KTILE) {
        __syncthreads();
        for (int i = threadIdx.x; i < BB * KTILE; i += 128) {
            int b = i / KTILE, kk = i % KTILE;
            s_z[i] = Z[(size_t)b * K + kt + kk];
        }
        __syncthreads();
        for (int kk = 0; kk < KTILE; kk += 4) {
            float w0 = W[(size_t)(kt + kk + 0) * N + j];
            float w1 = W[(size_t)(kt + kk + 1) * N + j];
            float w2 = W[(size_t)(kt + kk + 2) * N + j];
            float w3 = W[(size_t)(kt + kk + 3) * N + j];
#pragma unroll
            for (int b = 0; b < BB; b++) {
                float4 zz = *(const float4*)&s_z[b * KTILE + kk];
                acc[b] = fmaf(zz.x, w0, acc[b]);
                acc[b] = fmaf(zz.y, w1, acc[b]);
                acc[b] = fmaf(zz.z, w2, acc[b]);
                acc[b] = fmaf(zz.w, w3, acc[b]);
            }
        }
    }
#pragma unroll
    for (int b = 0; b < BB; b++) atomicAdd(&C[b * N + j], acc[b]);
}

__global__ void zero_kernel(float* __restrict__ p, int n)
{
    int i = blockIdx.x * 256 + threadIdx.x;
    if (i < n) p[i] = 0.f;
}
__global__ void bias_relu_kernel(float* __restrict__ C, const float* __restrict__ bias,
                                 int N, int total)
{
    int i = blockIdx.x * 256 + threadIdx.x;
    if (i < total) { float v = C[i] + bias[i % N]; C[i] = fmaxf(v, 0.f); }
}

extern "C" void kernel_launch(void* const* d_in, const int* in_sizes, int n_in,
                              void* d_out, int out_size)
{
    const float* x   = (const float*)d_in[0];
    const float* eps = (const float*)d_in[1];
    const float* ew0 = (const float*)d_in[2];
    const float* eb0 = (const float*)d_in[3];
    const float* ew1 = (const float*)d_in[4];
    const float* eb1 = (const float*)d_in[5];
    const float* ew2 = (const float*)d_in[6];
    const float* eb2 = (const float*)d_in[7];
    const float* dw0 = (const float*)d_in[8];
    const float* db0 = (const float*)d_in[9];
    const float* dw1 = (const float*)d_in[10];
    const float* db1 = (const float*)d_in[11];
    const float* dw2 = (const float*)d_in[12];
    const float* db2 = (const float*)d_in[13];
    const float* cb  = (const float*)d_in[14];
    float* out = (float*)d_out;

    uint16_t *p_xh, *p_xl, *p_w0h, *p_w0l, *p_w1h, *p_w1l, *p_h0h, *p_h0l, *p_a2h, *p_a2l;
    float *p_h1, *p_enc, *p_ze, *p_zq, *p_hd0, *p_hd1, *p_vq;
    cudaGetSymbolAddress((void**)&p_xh,  g_xh);
    cudaGetSymbolAddress((void**)&p_xl,  g_xl);
    cudaGetSymbolAddress((void**)&p_w0h, g_w0h);
    cudaGetSymbolAddress((void**)&p_w0l, g_w0l);
    cudaGetSymbolAddress((void**)&p_w1h, g_w1h);
    cudaGetSymbolAddress((void**)&p_w1l, g_w1l);
    cudaGetSymbolAddress((void**)&p_h0h, g_h0h);
    cudaGetSymbolAddress((void**)&p_h0l, g_h0l);
    cudaGetSymbolAddress((void**)&p_a2h, g_a2h);
    cudaGetSymbolAddress((void**)&p_a2l, g_a2l);
    cudaGetSymbolAddress((void**)&p_h1,  g_h1);
    cudaGetSymbolAddress((void**)&p_enc, g_enc);
    cudaGetSymbolAddress((void**)&p_ze,  g_ze);
    cudaGetSymbolAddress((void**)&p_zq,  g_zq);
    cudaGetSymbolAddress((void**)&p_hd0, g_hd0);
    cudaGetSymbolAddress((void**)&p_hd1, g_hd1);
    cudaGetSymbolAddress((void**)&p_vq,  g_vqpart);

    // pre-split: x in fragment layout (A of L0); weights transposed (B)
    split_frag<<<(MM*KP0/2 + 255)/256, 256>>>(x, p_xh, p_xl, FFE, KP0, MM*KP0/2);
    split_tr<<<(E0*KP0 + 255)/256, 256>>>(ew0, p_w0h, p_w0l, FFE, E0, KP0, E0*KP0);
    split_tr<<<(E1*E0 + 255)/256, 256>>>(ew1, p_w1h, p_w1l, E0, E1, E0, E1*E0);

    // encoder L0: A=x frags, writes h0 in fragment layout (A of L1)
    mma_gemm_bf<KP0, 1, 1><<<dim3(E0/128, MM/128), 256>>>(
        p_xh, p_xl, p_w0h, p_w0l, eb0, nullptr, p_h0h, p_h0l, E0);
    // encoder L1: A=h0 frags, fp32 out
    mma_gemm_bf<E0, 1, 0><<<dim3(E1/128, MM/128), 256>>>(
        p_h0h, p_h0l, p_w1h, p_w1l, eb1, p_h1, nullptr, nullptr, E1);
    // encoder head (exact fp32)
    sgemm_kernel<128,32,16,8,4,0><<<dim3(1, MM/128), 128>>>(p_h1, ew2, eb2, p_enc, MM, E2, E1);

    reparam_kernel<<<(MM*DD + 255)/256, 256>>>(p_enc, eps, out + MEAN_OFF, out + LV_OFF, p_ze);

    vq_kernel<<<NVQBLK, 128>>>(p_ze, cb, p_zq, p_vq);
    vq_reduce_kernel<<<1, 32>>>(p_vq, out + VQ_OFF);

    // decoder D0 / D1: exact fp32 split-K
    zero_kernel<<<(BB*DEC0 + 255)/256, 256>>>(p_hd0, BB*DEC0);
    skinny_splitk_kernel<64><<<dim3(DEC0/128, 16), 128>>>(p_zq, dw0, p_hd0, ZFD, DEC0, 576);
    bias_relu_kernel<<<(BB*DEC0 + 255)/256, 256>>>(p_hd0, db0, DEC0, BB*DEC0);

    zero_kernel<<<(BB*DEC1 + 255)/256, 256>>>(p_hd1, BB*DEC1);
    skinny_splitk_kernel<64><<<dim3(DEC1/128, 8), 128>>>(p_hd0, dw1, p_hd1, DEC0, DEC1, 128);
    bias_relu_kernel<<<(BB*DEC1 + 255)/256, 256>>>(p_hd1, db1, DEC1, BB*DEC1);

    // decoder D2 (row-major split A, unchanged)
    split_rm<<<(BB*DEC1 + 255)/256, 256>>>(p_hd1, p_a2h, p_a2l, DEC1, DEC1, BB*DEC1);
    mma_gemm_d2<<<NOUT/256, 256>>>(p_a2h, p_a2l, dw2, db2, out + REC_OFF);
}